// round 1
// baseline (speedup 1.0000x reference)
#include <cuda_runtime.h>
#include <math.h>

#define N_NODES 50000
#define N_EDGES 800000
#define DIM 128            // NODE_DIM == EDGE_LBL_DIM
#define OUT_DIM 256

// Scratch (allocation-free: __device__ globals)
__device__ float g_accum[N_NODES * DIM];          // 25.6 MB
__device__ int   g_deg[N_NODES + 2];              // pad to int4 multiple
__device__ int   g_counts[N_EDGES + 4];           // bincount(deg, length=E+1), padded

// ---------------------------------------------------------------------------
// Kernel 1: zero the scratch buffers (vectorized 16B stores)
// ---------------------------------------------------------------------------
#define A4 (N_NODES * DIM / 4)          // 1,600,000 float4
#define D4 ((N_NODES + 3) / 4)          // deg in int4 (padded array covers this)
#define C4 ((N_EDGES + 4) / 4)          // counts in int4

__global__ void zero_kernel() {
    int i = blockIdx.x * blockDim.x + threadIdx.x;
    if (i < A4) {
        ((float4*)g_accum)[i] = make_float4(0.f, 0.f, 0.f, 0.f);
    } else if (i < A4 + D4) {
        ((int4*)g_deg)[i - A4] = make_int4(0, 0, 0, 0);
    } else if (i < A4 + D4 + C4) {
        ((int4*)g_counts)[i - A4 - D4] = make_int4(0, 0, 0, 0);
    }
}

// ---------------------------------------------------------------------------
// Kernel 2: scatter-add edge labels into per-node accumulator.
// One warp per edge; each lane adds a float4 via vectorized REDG (no return).
// ---------------------------------------------------------------------------
__global__ void scatter_kernel(const float4* __restrict__ e_lbl,
                               const int* __restrict__ edge_dst) {
    int warp = (blockIdx.x * blockDim.x + threadIdx.x) >> 5;
    int lane = threadIdx.x & 31;
    if (warp >= N_EDGES) return;

    int dst = __ldg(&edge_dst[warp]);
    float4 v = e_lbl[(size_t)warp * 32 + lane];

    float* p = &g_accum[(size_t)dst * DIM + lane * 4];
    asm volatile("red.global.add.v4.f32 [%0], {%1, %2, %3, %4};"
                 :: "l"(p), "f"(v.x), "f"(v.y), "f"(v.z), "f"(v.w)
                 : "memory");

    if (lane == 0) atomicAdd(&g_deg[dst], 1);
}

// ---------------------------------------------------------------------------
// Kernel 3: degree histogram (bincount)
// ---------------------------------------------------------------------------
__global__ void hist_kernel() {
    int n = blockIdx.x * blockDim.x + threadIdx.x;
    if (n < N_NODES) {
        atomicAdd(&g_counts[g_deg[n]], 1);
    }
}

// ---------------------------------------------------------------------------
// Kernel 4: finalize.
// Thread layout: 64 float4-slots per node (32 for h, 32 for accum), so each
// warp handles a homogeneous half-row -> no intra-warp divergence.
// ---------------------------------------------------------------------------
__device__ __forceinline__ float elu1(float x) {
    return x > 0.f ? x : expm1f(x);
}

__global__ void finalize_kernel(const float4* __restrict__ h,
                                float4* __restrict__ out) {
    int idx = blockIdx.x * blockDim.x + threadIdx.x;   // over N_NODES * 64
    if (idx >= N_NODES * 64) return;

    int node = idx >> 6;
    int c4   = idx & 63;

    int d = g_deg[node];
    float4 r;
    if (d == 0) {
        r = make_float4(0.f, 0.f, 0.f, 0.f);
    } else if (c4 < 32) {
        r = h[(size_t)node * 32 + c4];
        r.x = elu1(r.x); r.y = elu1(r.y); r.z = elu1(r.z); r.w = elu1(r.w);
    } else {
        r = ((const float4*)g_accum)[(size_t)node * 32 + (c4 - 32)];
        float inv = 1.f / (float)g_counts[d];
        r.x = elu1(r.x * inv); r.y = elu1(r.y * inv);
        r.z = elu1(r.z * inv); r.w = elu1(r.w * inv);
    }
    out[idx] = r;
}

// ---------------------------------------------------------------------------
extern "C" void kernel_launch(void* const* d_in, const int* in_sizes, int n_in,
                              void* d_out, int out_size) {
    const float4* h        = (const float4*)d_in[0];
    const float4* e_lbl    = (const float4*)d_in[1];
    const int*    edge_dst = (const int*)d_in[2];
    float4*       out      = (float4*)d_out;

    (void)in_sizes; (void)n_in; (void)out_size;

    // 1. zero scratch
    {
        int total = A4 + D4 + C4;
        int threads = 256;
        int blocks = (total + threads - 1) / threads;
        zero_kernel<<<blocks, threads>>>();
    }
    // 2. scatter (1 warp per edge)
    {
        int threads = 256;                       // 8 warps/block
        int blocks = (N_EDGES + 7) / 8;          // 100000 blocks
        scatter_kernel<<<blocks, threads>>>(e_lbl, edge_dst);
    }
    // 3. degree histogram
    {
        int threads = 256;
        int blocks = (N_NODES + threads - 1) / threads;
        hist_kernel<<<blocks, threads>>>();
    }
    // 4. finalize
    {
        int total = N_NODES * 64;
        int threads = 256;
        int blocks = (total + threads - 1) / threads;
        finalize_kernel<<<blocks, threads>>>(h, out);
    }
}